// round 5
// baseline (speedup 1.0000x reference)
#include <cuda_runtime.h>
#include <cstdint>

#define NNODES 100000
#define NEDGES 640000
#define FIN 128
#define FOUT 64
#define BN_EPS 1e-5f
#define SCAN_BS 256
#define MAX_BLOCKS 512   // ceil(NNODES/SCAN_BS) = 391 < 512

// ---------------- scratch (static device globals; no runtime allocation) ----
__device__ float g_h[(size_t)NNODES * FIN];     // x @ W_gcn
__device__ float g_agg[(size_t)NNODES * FIN];   // aggregated messages
__device__ float g_t[(size_t)NNODES * FOUT];    // hidden after GEMM2
__device__ int   g_degi[NNODES];
__device__ float g_dinv[NNODES];
__device__ int   g_off[NNODES + 1];
__device__ int   g_cursor[NNODES];
__device__ int   g_bsum[MAX_BLOCKS];
__device__ int   g_boff[MAX_BLOCKS];
__device__ int   g_elist[NEDGES];
__device__ float g_sum1[FIN], g_sq1[FIN], g_a1[FIN], g_c1[FIN];
__device__ float g_sum2[FOUT], g_sq2[FOUT], g_a2[FOUT], g_c2[FOUT];

// ---------------- zero ------------------------------------------------------
__global__ void zero_kernel(int M) {
    int i = blockIdx.x * blockDim.x + threadIdx.x;
    for (int j = i; j < M; j += gridDim.x * blockDim.x) g_degi[j] = 0;
    if (i < FIN)  { g_sum1[i] = 0.f; g_sq1[i] = 0.f; }
    if (i < FOUT) { g_sum2[i] = 0.f; g_sq2[i] = 0.f; }
}

// ---------------- in-degree count -------------------------------------------
__global__ void deg_kernel(const int* __restrict__ dst, int E, int M) {
    int e = blockIdx.x * blockDim.x + threadIdx.x;
    if (e < E) {
        int d = dst[e];
        if ((unsigned)d < (unsigned)M) atomicAdd(&g_degi[d], 1);
    }
}

// ---------------- prefix scan (3 kernels) -----------------------------------
__global__ void scan1_kernel(int M) {
    __shared__ int sh[SCAN_BS];
    int i = blockIdx.x * SCAN_BS + threadIdx.x;
    int v = (i < M) ? g_degi[i] : 0;
    sh[threadIdx.x] = v;
    __syncthreads();
    #pragma unroll
    for (int ofs = 1; ofs < SCAN_BS; ofs <<= 1) {
        int t = 0;
        if (threadIdx.x >= ofs) t = sh[threadIdx.x - ofs];
        __syncthreads();
        sh[threadIdx.x] += t;
        __syncthreads();
    }
    if (i < M) g_off[i] = sh[threadIdx.x] - v;          // exclusive within block
    if (threadIdx.x == SCAN_BS - 1) g_bsum[blockIdx.x] = sh[SCAN_BS - 1];
}

__global__ void scan2_kernel(int NB) {
    __shared__ int sh[MAX_BLOCKS];
    int t = threadIdx.x;
    int v = (t < NB) ? g_bsum[t] : 0;
    sh[t] = v;
    __syncthreads();
    #pragma unroll
    for (int ofs = 1; ofs < MAX_BLOCKS; ofs <<= 1) {
        int u = 0;
        if (t >= ofs) u = sh[t - ofs];
        __syncthreads();
        sh[t] += u;
        __syncthreads();
    }
    if (t < NB) g_boff[t] = sh[t] - v;                   // exclusive block offset
}

__global__ void scan3_kernel(int M, int E) {
    int i = blockIdx.x * blockDim.x + threadIdx.x;
    if (i < M) {
        int o = g_off[i] + g_boff[i / SCAN_BS];
        g_off[i] = o;
        g_cursor[i] = o;
        g_dinv[i] = rsqrtf((float)g_degi[i] + 1.0f);  // +1 = self loop (fused)
    }
    if (i == 0) g_off[M] = E;
}

// ---------------- edge-list fill --------------------------------------------
__global__ void fill_kernel(const int* __restrict__ src, const int* __restrict__ dst,
                            int E, int M) {
    int e = blockIdx.x * blockDim.x + threadIdx.x;
    if (e < E) {
        int s = src[e];
        int d = dst[e];
        if ((unsigned)s < (unsigned)M && (unsigned)d < (unsigned)M) {
            int p = atomicAdd(&g_cursor[d], 1);
            g_elist[p] = s;
        }
    }
}

// ---------------- gather: agg[d] = dinv[d]*sum(dinv[s]*h[s]) + dinv[d]^2*h[d]
// one warp per node; lane l covers feature columns 4l..4l+3; 2-way edge ILP
__global__ void gather_kernel(int M) {
    int warp = (blockIdx.x * blockDim.x + threadIdx.x) >> 5;
    int lane = threadIdx.x & 31;
    if (warp >= M) return;
    int d = warp;
    int e0 = g_off[d];
    int e1 = g_cursor[d];
    float4 acc0 = make_float4(0.f, 0.f, 0.f, 0.f);
    float4 acc1 = make_float4(0.f, 0.f, 0.f, 0.f);
    int e = e0;
    for (; e + 1 < e1; e += 2) {
        int s0 = g_elist[e];
        int s1 = g_elist[e + 1];
        float w0 = g_dinv[s0];
        float w1 = g_dinv[s1];
        float4 v0 = *(const float4*)&g_h[(size_t)s0 * FIN + lane * 4];
        float4 v1 = *(const float4*)&g_h[(size_t)s1 * FIN + lane * 4];
        acc0.x = fmaf(v0.x, w0, acc0.x); acc1.x = fmaf(v1.x, w1, acc1.x);
        acc0.y = fmaf(v0.y, w0, acc0.y); acc1.y = fmaf(v1.y, w1, acc1.y);
        acc0.z = fmaf(v0.z, w0, acc0.z); acc1.z = fmaf(v1.z, w1, acc1.z);
        acc0.w = fmaf(v0.w, w0, acc0.w); acc1.w = fmaf(v1.w, w1, acc1.w);
    }
    if (e < e1) {
        int s0 = g_elist[e];
        float w0 = g_dinv[s0];
        float4 v0 = *(const float4*)&g_h[(size_t)s0 * FIN + lane * 4];
        acc0.x = fmaf(v0.x, w0, acc0.x);
        acc0.y = fmaf(v0.y, w0, acc0.y);
        acc0.z = fmaf(v0.z, w0, acc0.z);
        acc0.w = fmaf(v0.w, w0, acc0.w);
    }
    float wd = g_dinv[d];
    float4 vs = *(const float4*)&g_h[(size_t)d * FIN + lane * 4];
    float4 o;
    o.x = wd * (acc0.x + acc1.x) + wd * wd * vs.x;
    o.y = wd * (acc0.y + acc1.y) + wd * wd * vs.y;
    o.z = wd * (acc0.z + acc1.z) + wd * wd * vs.z;
    o.w = wd * (acc0.w + acc1.w) + wd * wd * vs.w;
    *(float4*)&g_agg[(size_t)d * FIN + lane * 4] = o;
}

// ---------------- per-column sum / sumsq ------------------------------------
template <int F>
__global__ void stats_kernel(const float* __restrict__ X, int M,
                             float* __restrict__ sum, float* __restrict__ sq) {
    constexpr int RP = 256 / F;
    int col  = threadIdx.x % F;
    int rsub = threadIdx.x / F;
    float s = 0.f, q = 0.f;
    for (int r = blockIdx.x * RP + rsub; r < M; r += gridDim.x * RP) {
        float v = X[(size_t)r * F + col];
        s += v; q += v * v;
    }
    __shared__ float sh[256];
    sh[threadIdx.x] = s; __syncthreads();
    if (rsub == 0) {
        #pragma unroll
        for (int k = 1; k < RP; k++) s += sh[k * F + col];
    }
    __syncthreads();
    sh[threadIdx.x] = q; __syncthreads();
    if (rsub == 0) {
        #pragma unroll
        for (int k = 1; k < RP; k++) q += sh[k * F + col];
        atomicAdd(&sum[col], s);
        atomicAdd(&sq[col],  q);
    }
}

template <int F>
__global__ void finalize_kernel(const float* __restrict__ sum, const float* __restrict__ sq,
                                const float* __restrict__ gamma, const float* __restrict__ beta,
                                int M, float* __restrict__ a, float* __restrict__ c) {
    int i = threadIdx.x;
    if (i < F) {
        float mean = sum[i] / (float)M;
        float var  = sq[i] / (float)M - mean * mean;
        float s = gamma[i] * rsqrtf(var + BN_EPS);
        a[i] = s;
        c[i] = beta[i] - mean * s;
    }
}

// ---------------- double-buffered SGEMM -------------------------------------
// C[M,N] = act(A)[M,K] @ B[K,N]; act = relu(a*x+c) per K-column when BNIN.
template <int N, int K, bool BNIN, bool BIAS>
__global__ __launch_bounds__(256, 2) void sgemm_kernel(
    const float* __restrict__ A, const float* __restrict__ B, float* __restrict__ C,
    int M, const float* __restrict__ sc, const float* __restrict__ shf,
    const float* __restrict__ bias) {
    constexpr int BM = 128, BK = 16, TM = 8, TN = N / 16;
    constexpr int NT = K / BK;          // k-tiles
    constexpr int APT = 2;              // A float4 per thread (128*16/4/256)
    constexpr int BPT = (BK * N / 4) / 256;  // B float4 per thread (2 for N=128, 1 for 64)

    __shared__ float As[2][BK][BM + 4];
    __shared__ float Bs[2][BK][N];
    __shared__ float s_sc[K], s_sh[K];

    int tid = threadIdx.x;
    if (BNIN) {
        for (int i = tid; i < K; i += 256) { s_sc[i] = sc[i]; s_sh[i] = shf[i]; }
        __syncthreads();
    }

    int tx = tid & 15, ty = tid >> 4;
    int row0 = blockIdx.x * BM;

    // A-load mapping: float4 index f -> row = f>>2, kofs = (f&3)*4
    int a_r[APT], a_k[APT];
    bool a_ok[APT];
    #pragma unroll
    for (int p = 0; p < APT; p++) {
        int f = tid + p * 256;
        a_r[p] = f >> 2;
        a_k[p] = (f & 3) * 4;
        a_ok[p] = (row0 + a_r[p]) < M;
    }
    // B-load mapping: float4 index g -> kr = g/(N/4), c4 = (g%(N/4))*4
    int b_kr[2], b_c4[2];
    #pragma unroll
    for (int p = 0; p < BPT; p++) {
        int g = tid + p * 256;
        b_kr[p] = g / (N / 4);
        b_c4[p] = (g % (N / 4)) * 4;
    }

    float4 pa[APT], pb[2];

    // ---- load tile 0 ----
    #pragma unroll
    for (int p = 0; p < APT; p++) {
        pa[p] = make_float4(0.f, 0.f, 0.f, 0.f);
        if (a_ok[p]) pa[p] = *(const float4*)&A[(size_t)(row0 + a_r[p]) * K + a_k[p]];
    }
    #pragma unroll
    for (int p = 0; p < BPT; p++)
        pb[p] = *(const float4*)&B[(size_t)b_kr[p] * N + b_c4[p]];

    // store tile 0
    #pragma unroll
    for (int p = 0; p < APT; p++) {
        float4 v = pa[p];
        if (BNIN) {
            int kb = a_k[p];
            v.x = fmaxf(fmaf(v.x, s_sc[kb + 0], s_sh[kb + 0]), 0.f);
            v.y = fmaxf(fmaf(v.y, s_sc[kb + 1], s_sh[kb + 1]), 0.f);
            v.z = fmaxf(fmaf(v.z, s_sc[kb + 2], s_sh[kb + 2]), 0.f);
            v.w = fmaxf(fmaf(v.w, s_sc[kb + 3], s_sh[kb + 3]), 0.f);
        }
        As[0][a_k[p] + 0][a_r[p]] = v.x;
        As[0][a_k[p] + 1][a_r[p]] = v.y;
        As[0][a_k[p] + 2][a_r[p]] = v.z;
        As[0][a_k[p] + 3][a_r[p]] = v.w;
    }
    #pragma unroll
    for (int p = 0; p < BPT; p++)
        *(float4*)&Bs[0][b_kr[p]][b_c4[p]] = pb[p];
    __syncthreads();

    float acc[TM][TN];
    #pragma unroll
    for (int i = 0; i < TM; i++)
        #pragma unroll
        for (int j = 0; j < TN; j++) acc[i][j] = 0.f;

    #pragma unroll
    for (int t = 0; t < NT; t++) {
        int buf = t & 1;
        int k0n = (t + 1) * BK;
        // prefetch next tile into registers
        if (t + 1 < NT) {
            #pragma unroll
            for (int p = 0; p < APT; p++) {
                pa[p] = make_float4(0.f, 0.f, 0.f, 0.f);
                if (a_ok[p]) pa[p] = *(const float4*)&A[(size_t)(row0 + a_r[p]) * K + k0n + a_k[p]];
            }
            #pragma unroll
            for (int p = 0; p < BPT; p++)
                pb[p] = *(const float4*)&B[(size_t)(k0n + b_kr[p]) * N + b_c4[p]];
        }
        // compute on current buffer
        #pragma unroll
        for (int kk = 0; kk < BK; kk++) {
            float a[TM], b[TN];
            *(float4*)&a[0] = *(const float4*)&As[buf][kk][ty * TM];
            *(float4*)&a[4] = *(const float4*)&As[buf][kk][ty * TM + 4];
            #pragma unroll
            for (int j = 0; j < TN; j += 4)
                *(float4*)&b[j] = *(const float4*)&Bs[buf][kk][tx * TN + j];
            #pragma unroll
            for (int i = 0; i < TM; i++)
                #pragma unroll
                for (int j = 0; j < TN; j++)
                    acc[i][j] = fmaf(a[i], b[j], acc[i][j]);
        }
        // store next tile
        if (t + 1 < NT) {
            int nb = buf ^ 1;
            #pragma unroll
            for (int p = 0; p < APT; p++) {
                float4 v = pa[p];
                if (BNIN) {
                    int kb = k0n + a_k[p];
                    v.x = fmaxf(fmaf(v.x, s_sc[kb + 0], s_sh[kb + 0]), 0.f);
                    v.y = fmaxf(fmaf(v.y, s_sc[kb + 1], s_sh[kb + 1]), 0.f);
                    v.z = fmaxf(fmaf(v.z, s_sc[kb + 2], s_sh[kb + 2]), 0.f);
                    v.w = fmaxf(fmaf(v.w, s_sc[kb + 3], s_sh[kb + 3]), 0.f);
                }
                As[nb][a_k[p] + 0][a_r[p]] = v.x;
                As[nb][a_k[p] + 1][a_r[p]] = v.y;
                As[nb][a_k[p] + 2][a_r[p]] = v.z;
                As[nb][a_k[p] + 3][a_r[p]] = v.w;
            }
            #pragma unroll
            for (int p = 0; p < BPT; p++)
                *(float4*)&Bs[nb][b_kr[p]][b_c4[p]] = pb[p];
            __syncthreads();
        }
    }

    float bj[TN];
    if (BIAS) {
        #pragma unroll
        for (int j = 0; j < TN; j++) bj[j] = bias[tx * TN + j];
    }
    #pragma unroll
    for (int i = 0; i < TM; i++) {
        int grow = row0 + ty * TM + i;
        if (grow < M) {
            #pragma unroll
            for (int j = 0; j < TN; j += 4) {
                float4 v;
                v.x = acc[i][j]; v.y = acc[i][j + 1];
                v.z = acc[i][j + 2]; v.w = acc[i][j + 3];
                if (BIAS) { v.x += bj[j]; v.y += bj[j + 1]; v.z += bj[j + 2]; v.w += bj[j + 3]; }
                *(float4*)&C[(size_t)grow * N + tx * TN + j] = v;
            }
        }
    }
}

// ---------------- launch ----------------------------------------------------
extern "C" void kernel_launch(void* const* d_in, const int* in_sizes, int n_in,
                              void* d_out, int out_size) {
    const float* x     = (const float*)d_in[0];
    const int*   ei    = (const int*)d_in[1];
    const float* W_gcn = (const float*)d_in[2];
    // d_in[3] = b_gcn : exactly absorbed by BN1 (mean-subtraction) -> unused
    const float* bn_g  = (const float*)d_in[4];
    const float* bn_b  = (const float*)d_in[5];
    const float* W1    = (const float*)d_in[6];
    // d_in[7] = b1    : exactly absorbed by BN2 -> unused
    const float* mg    = (const float*)d_in[8];
    const float* mb    = (const float*)d_in[9];
    const float* W2    = (const float*)d_in[10];
    const float* b2    = (const float*)d_in[11];
    float* out = (float*)d_out;

    int M = in_sizes[0] / FIN;
    int E = in_sizes[1] / 2;
    const int* src = ei;
    const int* dst = ei + E;
    int NB = (M + SCAN_BS - 1) / SCAN_BS;

    void *p_h, *p_agg, *p_t, *p_sum1, *p_sq1, *p_a1, *p_c1, *p_sum2, *p_sq2, *p_a2, *p_c2;
    cudaGetSymbolAddress(&p_h, g_h);
    cudaGetSymbolAddress(&p_agg, g_agg);
    cudaGetSymbolAddress(&p_t, g_t);
    cudaGetSymbolAddress(&p_sum1, g_sum1);
    cudaGetSymbolAddress(&p_sq1, g_sq1);
    cudaGetSymbolAddress(&p_a1, g_a1);
    cudaGetSymbolAddress(&p_c1, g_c1);
    cudaGetSymbolAddress(&p_sum2, g_sum2);
    cudaGetSymbolAddress(&p_sq2, g_sq2);
    cudaGetSymbolAddress(&p_a2, g_a2);
    cudaGetSymbolAddress(&p_c2, g_c2);

    // index machinery
    zero_kernel<<<256, 256>>>(M);
    deg_kernel<<<(E + 255) / 256, 256>>>(dst, E, M);
    scan1_kernel<<<NB, SCAN_BS>>>(M);
    scan2_kernel<<<1, MAX_BLOCKS>>>(NB);
    scan3_kernel<<<NB, SCAN_BS>>>(M, E);
    fill_kernel<<<(E + 255) / 256, 256>>>(src, dst, E, M);

    // GEMM1: h = x @ W_gcn
    sgemm_kernel<FIN, FIN, false, false><<<(M + 127) / 128, 256>>>(
        x, W_gcn, (float*)p_h, M, nullptr, nullptr, nullptr);

    // CSR gather
    gather_kernel<<<(M * 32 + 255) / 256, 256>>>(M);

    // BN1 stats
    stats_kernel<FIN><<<1024, 256>>>((const float*)p_agg, M, (float*)p_sum1, (float*)p_sq1);
    finalize_kernel<FIN><<<1, 128>>>((const float*)p_sum1, (const float*)p_sq1,
                                     bn_g, bn_b, M, (float*)p_a1, (float*)p_c1);

    // GEMM2: t = relu(BN1(agg)) @ W1   (b1 absorbed by BN2)
    sgemm_kernel<FOUT, FIN, true, false><<<(M + 127) / 128, 256>>>(
        (const float*)p_agg, W1, (float*)p_t, M,
        (const float*)p_a1, (const float*)p_c1, nullptr);

    // BN2 stats
    stats_kernel<FOUT><<<1024, 256>>>((const float*)p_t, M, (float*)p_sum2, (float*)p_sq2);
    finalize_kernel<FOUT><<<1, 64>>>((const float*)p_sum2, (const float*)p_sq2,
                                     mg, mb, M, (float*)p_a2, (float*)p_c2);

    // GEMM3: out = relu(BN2(t)) @ W2 + b2
    sgemm_kernel<FOUT, FOUT, true, true><<<(M + 127) / 128, 256>>>(
        (const float*)p_t, W2, out, M,
        (const float*)p_a2, (const float*)p_c2, b2);
}